// round 1
// baseline (speedup 1.0000x reference)
#include <cuda_runtime.h>

#define NB     320
#define NANCH  5
#define NHW    26
#define AREA   676          // 26*26
#define KPOS   3380         // 5*676
#define CELLS  (NB*KPOS)
#define NBOX   50
#define NENT   (NB*NBOX)
#define BS     16
#define CSZ    20
#define NMETA  20
#define DWROWS 64
#define DWCOLS 1024

__constant__ float c_aw[5] = {1.3221f, 3.19275f, 5.05587f, 9.47112f, 11.2364f};
__constant__ float c_ah[5] = {1.73145f, 4.00944f, 8.09892f, 4.84053f, 10.0071f};

__device__ double g_acc;
__device__ int    g_slot[CELLS];
__device__ float  e_tx[NENT], e_ty[NENT], e_tw[NENT], e_th[NENT], e_tconf[NENT];
__device__ int    e_cell[NENT];
__device__ float4 g_bbox[NENT];
__device__ float  g_barea[NENT];
__device__ float  g_enews[NMETA*DWCOLS];
__device__ int    g_cnt[NMETA];

__device__ __forceinline__ float sigmoidf(float v){ return 1.f/(1.f+__expf(-v)); }

__device__ __forceinline__ void block_reduce_add(float v){
    __shared__ float red[256];
    int tid = threadIdx.x;
    red[tid] = v; __syncthreads();
    #pragma unroll
    for(int s=128; s>0; s>>=1){ if(tid<s) red[tid]+=red[tid+s]; __syncthreads(); }
    if(tid==0) atomicAdd(&g_acc, (double)red[0]);
}

// ---------------- K0: init ----------------
__global__ void k_init(){
    int i = blockIdx.x*blockDim.x + threadIdx.x;
    if(i==0) g_acc = 0.0;
    for(; i<CELLS; i += gridDim.x*blockDim.x) g_slot[i] = -1;
}

// ---------------- K1a: per-(batch,box) entry table ----------------
__global__ void k_entries(const float* __restrict__ out, const float* __restrict__ tgt){
    int e = blockIdx.x*blockDim.x + threadIdx.x;
    if(e >= NENT) return;
    int b = e / NBOX;
    const float* g = tgt + e*5;
    float g1 = g[1];
    if(g1 == 0.0f){
        e_cell[e] = -1;
        g_bbox[e] = make_float4(3e9f, 3e9f, 3e9f, 3e9f);  // degenerate: never overlaps
        g_barea[e] = 1.0f;
        return;
    }
    float gx = g1*26.f, gy = g[2]*26.f, gw = g[3]*26.f, gh = g[4]*26.f;
    g_bbox[e]  = make_float4(gx-0.5f*gw, gy-0.5f*gh, gx+0.5f*gw, gy+0.5f*gh);
    g_barea[e] = 0.6f*gw*gh;

    // best anchor (first max wins, like argmax)
    int bn = 0; float best = -1.f;
    #pragma unroll
    for(int a=0; a<5; a++){
        float inter = fminf(gw, c_aw[a]) * fminf(gh, c_ah[a]);
        float iou = inter / (gw*gh + c_aw[a]*c_ah[a] - inter);
        if(iou > best){ best = iou; bn = a; }
    }
    int gi = (int)gx; gi = min(max(gi,0), NHW-1);
    int gj = (int)gy; gj = min(max(gj,0), NHW-1);

    int base = ((b*5+bn)*6)*AREA + gj*NHW + gi;
    float px = sigmoidf(out[base])          + (float)gi;
    float py = sigmoidf(out[base+AREA])     + (float)gj;
    float pw = __expf(out[base+2*AREA]) * c_aw[bn];
    float ph = __expf(out[base+3*AREA]) * c_ah[bn];

    float cw  = fminf(gx+0.5f*gw, px+0.5f*pw) - fmaxf(gx-0.5f*gw, px-0.5f*pw);
    float chh = fminf(gy+0.5f*gh, py+0.5f*ph) - fmaxf(gy-0.5f*gh, py-0.5f*ph);
    float inter = (cw>0.f && chh>0.f) ? cw*chh : 0.f;
    float iou = inter / (gw*gh + pw*ph - inter);

    e_tx[e] = gx - (float)gi;
    e_ty[e] = gy - (float)gj;
    e_tw[e] = logf(gw / c_aw[bn]);
    e_th[e] = logf(gh / c_ah[bn]);
    e_tconf[e] = iou;
    e_cell[e] = b*KPOS + bn*AREA + gj*NHW + gi;
}

// ---------------- K1b: sequential scatter (last box wins, per batch) ----------------
__global__ void k_scatter(){
    int b = blockIdx.x*blockDim.x + threadIdx.x;
    if(b >= NB) return;
    for(int t=0; t<NBOX; t++){
        int c = e_cell[b*NBOX + t];
        if(c >= 0) g_slot[c] = b*NBOX + t;
    }
}

// ---------------- K2: main per-cell losses ----------------
__global__ void __launch_bounds__(256) k_main(const float* __restrict__ out){
    int b  = blockIdx.y;
    int lc = blockIdx.x*256 + threadIdx.x;
    __shared__ float4 sb[NBOX];
    __shared__ float  sa[NBOX];
    if(threadIdx.x < NBOX){
        sb[threadIdx.x] = g_bbox[b*NBOX + threadIdx.x];
        sa[threadIdx.x] = g_barea[b*NBOX + threadIdx.x];
    }
    __syncthreads();

    float local = 0.f;
    if(lc < KPOS){
        int a = lc / AREA; int r = lc - a*AREA;
        const float* p = out + ((b*5+a)*6)*AREA + r;
        float xv = sigmoidf(p[0]);
        float yv = sigmoidf(p[AREA]);
        float wv = p[2*AREA];
        float hv = p[3*AREA];
        float cv = sigmoidf(p[4*AREA]);
        int j = r / NHW, i = r - j*NHW;
        float pw = __expf(wv)*c_aw[a], ph = __expf(hv)*c_ah[a];
        float px = xv + (float)i,  py = yv + (float)j;
        float px1 = px - 0.5f*pw, px2 = px + 0.5f*pw;
        float py1 = py - 0.5f*ph, py2 = py + 0.5f*ph;
        float pa06 = 0.6f*pw*ph;

        bool silent = false;
        #pragma unroll 10
        for(int t=0; t<NBOX; t++){
            float4 bb = sb[t];
            float cw  = fminf(px2, bb.z) - fmaxf(px1, bb.x);
            float chh = fminf(py2, bb.w) - fmaxf(py1, bb.y);
            // iou > 0.6  <=>  1.6*inter > 0.6*(pa+ga)
            silent |= (cw > 0.f) & (chh > 0.f) & (1.6f*(cw*chh) > pa06 + sa[t]);
        }

        int slot = g_slot[b*KPOS + lc];
        float tx=0.5f, ty=0.5f, tw=0.f, th=0.f, tc=0.f;
        float cm = silent ? 0.f : 1.f;
        if(slot >= 0){
            tx = e_tx[slot]; ty = e_ty[slot]; tw = e_tw[slot];
            th = e_th[slot]; tc = e_tconf[slot]; cm = 5.f;
        }
        float dx = xv - tx, dy = yv - ty, dwv = wv - tw, dh = hv - th, dc = cv - tc;
        local = 0.5f*(dx*dx + dy*dy + dwv*dwv + dh*dh + cm*dc*dc);
    }
    block_reduce_add(local);
}

// ---------------- K3: class loss (log-softmax over the 20-image group) ----------------
__global__ void __launch_bounds__(256) k_cls(const float* __restrict__ out){
    int idx = blockIdx.x*256 + threadIdx.x;
    float local = 0.f;
    if(idx < BS*KPOS){
        int bsi = idx / KPOS; int k = idx - bsi*KPOS;
        int a = k / AREA; int r = k - a*AREA;
        float v[CSZ]; float m = -3.4e38f;
        #pragma unroll
        for(int c=0; c<CSZ; c++){
            int bb = bsi*CSZ + c;
            v[c] = out[(bb*30 + a*6 + 5)*AREA + r];
            m = fmaxf(m, v[c]);
        }
        float s = 0.f;
        #pragma unroll
        for(int c=0; c<CSZ; c++) s += __expf(v[c]-m);
        float lse = m + __logf(s);
        #pragma unroll
        for(int c=0; c<CSZ; c++){
            if(g_slot[(bsi*CSZ + c)*KPOS + k] >= 0) local += lse - v[c];
        }
    }
    block_reduce_add(local);
}

// ---------------- K4a: class-mean embeddings ----------------
__global__ void k_enews(const float* __restrict__ dw, const int* __restrict__ ids){
    __shared__ int sids[DWROWS];
    int tid = threadIdx.x;
    if(tid < DWROWS) sids[tid] = ids[tid];
    __syncthreads();
    int col = blockIdx.x*blockDim.x + tid;
    if(col >= DWCOLS) return;
    float f[DWROWS];
    #pragma unroll
    for(int r=0; r<DWROWS; r++) f[r] = dw[r*DWCOLS + col];
    for(int c=0; c<NMETA; c++){
        float s = 0.f; int n = 0;
        #pragma unroll
        for(int r=0; r<DWROWS; r++){ if(sids[r]==c){ s += f[r]; n++; } }
        g_enews[c*DWCOLS + col] = s / (float)max(n, 1);
        if(col == 0) g_cnt[c] = n;
    }
}

// ---------------- K4b: "same" loss ----------------
__global__ void __launch_bounds__(256) k_same(const float* __restrict__ dw, const int* __restrict__ ids){
    int idx = blockIdx.x*256 + threadIdx.x;
    float v = 0.f;
    if(idx < DWROWS*DWCOLS){
        int r = idx >> 10, c = idx & 1023;
        float d = dw[idx] - g_enews[ids[r]*DWCOLS + c];
        v = d*d;
    }
    block_reduce_add(v);
}

// ---------------- K4c: pairwise distances + "different" loss (subtracted) ----------------
__global__ void __launch_bounds__(256) k_diff(){
    int i = blockIdx.x; int tid = threadIdx.x;
    float part[NMETA];
    #pragma unroll
    for(int j=0; j<NMETA; j++) part[j] = 0.f;
    for(int col=tid; col<DWCOLS; col+=256){
        float ei = g_enews[i*DWCOLS + col];
        #pragma unroll
        for(int j=0; j<NMETA; j++){
            float df = ei - g_enews[j*DWCOLS + col];
            part[j] += df*df;
        }
    }
    __shared__ float red[256];
    __shared__ float dmat[NMETA];
    for(int j=0; j<NMETA; j++){
        red[tid] = part[j]; __syncthreads();
        #pragma unroll
        for(int s=128; s>0; s>>=1){ if(tid<s) red[tid]+=red[tid+s]; __syncthreads(); }
        if(tid==0) dmat[j] = red[0];
        __syncthreads();
    }
    if(tid == 0){
        bool pi = g_cnt[i] > 0;
        float dmin = 3.4e38f; bool any = false;
        for(int j=0; j<NMETA; j++){
            bool vp = pi && (g_cnt[j] > 0) && (j != i);
            if(vp){ any = true; dmin = fminf(dmin, dmat[j]); }
        }
        if(any) atomicAdd(&g_acc, -(double)dmin);
    }
}

// ---------------- K5: write output ----------------
__global__ void k_final(float* out){
    if(threadIdx.x == 0) out[0] = (float)g_acc;
}

extern "C" void kernel_launch(void* const* d_in, const int* in_sizes, int n_in,
                              void* d_out, int out_size){
    const float* outp = (const float*)d_in[0];   // (320,30,26,26)
    const float* tgt  = (const float*)d_in[1];   // (16,20,250) == (320,50,5)
    const float* dwp  = (const float*)d_in[2];   // (1,64,1024)
    const int*   ids  = (const int*)d_in[3];     // (64,)
    float* res = (float*)d_out;

    k_init<<<512, 256>>>();
    k_entries<<<(NENT+255)/256, 256>>>(outp, tgt);
    k_scatter<<<1, NB>>>();
    {
        dim3 grid((KPOS+255)/256, NB);
        k_main<<<grid, 256>>>(outp);
    }
    k_cls<<<(BS*KPOS+255)/256, 256>>>(outp);
    k_enews<<<(DWCOLS+255)/256, 256>>>(dwp, ids);
    k_same<<<(DWROWS*DWCOLS+255)/256, 256>>>(dwp, ids);
    k_diff<<<NMETA, 256>>>();
    k_final<<<1, 32>>>(res);
}

// round 2
// speedup vs baseline: 1.6297x; 1.6297x over previous
#include <cuda_runtime.h>

#define NB     320
#define NHW    26
#define AREA   676          // 26*26
#define KPOS   3380         // 5*676
#define CELLS  (NB*KPOS)
#define NBOX   50
#define NENT   (NB*NBOX)
#define BS     16
#define CSZ    20
#define NMETA  20
#define DWROWS 64
#define DWCOLS 1024

// kernel A block layout
#define A_INIT 512
#define A_ENT  63
#define A_ENEW 20
#define A_BLOCKS (A_INIT + A_ENT + A_ENEW)
// kernel B block layout
#define B_SCAT 2
#define B_SAME 256
#define B_DIFF 20
#define B_BLOCKS (B_SCAT + B_SAME + B_DIFF)
// kernel C block layout
#define MAIN_BPB 14
#define C_MAIN (NB*MAIN_BPB)     // 4480
#define C_CLS  212               // ceil(16*3380/256)
#define C_BLOCKS (C_MAIN + C_CLS)

__constant__ float c_aw[5] = {1.3221f, 3.19275f, 5.05587f, 9.47112f, 11.2364f};
__constant__ float c_ah[5] = {1.73145f, 4.00944f, 8.09892f, 4.84053f, 10.0071f};

__device__ double g_acc;
__device__ int    g_done;
__device__ int    g_slot[CELLS];
__device__ float  e_tx[NENT], e_ty[NENT], e_tw[NENT], e_th[NENT], e_tconf[NENT];
__device__ int    e_cell[NENT];
__device__ float4 g_bbox[NENT];
__device__ float  g_sarea[NENT];   // 0.375 * gw*gh  (threshold-scaled)
__device__ float  g_enews[NMETA*DWCOLS];
__device__ int    g_cnt[NMETA];

__device__ __forceinline__ float sigmoidf(float v){ return 1.f/(1.f+__expf(-v)); }

// ================= Kernel A: init + entry table + class means =================
__global__ void __launch_bounds__(256) kA(const float* __restrict__ out,
                                          const float* __restrict__ tgt,
                                          const float* __restrict__ dw,
                                          const int*   __restrict__ ids){
    int blk = blockIdx.x, tid = threadIdx.x;
    if(blk < A_INIT){
        if(blk == 0 && tid == 0){ g_acc = 0.0; g_done = 0; }
        for(int i = blk*256 + tid; i < CELLS; i += A_INIT*256) g_slot[i] = -1;
    } else if(blk < A_INIT + A_ENT){
        int e = (blk - A_INIT)*256 + tid;
        if(e >= NENT) return;
        int b = e / NBOX;
        const float* g = tgt + e*5;
        float g1 = g[1];
        if(g1 == 0.0f){
            e_cell[e]  = -1;
            g_bbox[e]  = make_float4(3e9f, 3e9f, 3e9f, 3e9f);  // degenerate
            g_sarea[e] = 1.0f;
            return;
        }
        float gx = g1*26.f, gy = g[2]*26.f, gw = g[3]*26.f, gh = g[4]*26.f;
        g_bbox[e]  = make_float4(gx-0.5f*gw, gy-0.5f*gh, gx+0.5f*gw, gy+0.5f*gh);
        g_sarea[e] = 0.375f*gw*gh;

        int bn = 0; float best = -1.f;
        #pragma unroll
        for(int a=0; a<5; a++){
            float inter = fminf(gw, c_aw[a]) * fminf(gh, c_ah[a]);
            float iou = inter / (gw*gh + c_aw[a]*c_ah[a] - inter);
            if(iou > best){ best = iou; bn = a; }
        }
        int gi = (int)gx; gi = min(max(gi,0), NHW-1);
        int gj = (int)gy; gj = min(max(gj,0), NHW-1);

        int base = ((b*5+bn)*6)*AREA + gj*NHW + gi;
        float px = sigmoidf(out[base])          + (float)gi;
        float py = sigmoidf(out[base+AREA])     + (float)gj;
        float pw = __expf(out[base+2*AREA]) * c_aw[bn];
        float ph = __expf(out[base+3*AREA]) * c_ah[bn];

        float cw  = fminf(gx+0.5f*gw, px+0.5f*pw) - fmaxf(gx-0.5f*gw, px-0.5f*pw);
        float chh = fminf(gy+0.5f*gh, py+0.5f*ph) - fmaxf(gy-0.5f*gh, py-0.5f*ph);
        float inter = (cw>0.f && chh>0.f) ? cw*chh : 0.f;
        float iou = inter / (gw*gh + pw*ph - inter);

        e_tx[e] = gx - (float)gi;
        e_ty[e] = gy - (float)gj;
        e_tw[e] = logf(gw / c_aw[bn]);
        e_th[e] = logf(gh / c_ah[bn]);
        e_tconf[e] = iou;
        e_cell[e] = b*KPOS + bn*AREA + gj*NHW + gi;
    } else {
        // per-class mean embeddings: one block per class
        int c = blk - (A_INIT + A_ENT);
        __shared__ int sids[DWROWS];
        if(tid < DWROWS) sids[tid] = ids[tid];
        __syncthreads();
        int n = 0;
        #pragma unroll
        for(int r=0; r<DWROWS; r++) n += (sids[r] == c);
        if(tid == 0) g_cnt[c] = n;
        float inv = 1.f / (float)max(n, 1);
        for(int col = tid; col < DWCOLS; col += 256){
            float s = 0.f;
            #pragma unroll
            for(int r=0; r<DWROWS; r++){
                if(sids[r] == c) s += dw[r*DWCOLS + col];
            }
            g_enews[c*DWCOLS + col] = s * inv;
        }
    }
}

// ================= Kernel B: scatter + same + diff =================
__global__ void __launch_bounds__(256) kB(const float* __restrict__ dw,
                                          const int*   __restrict__ ids){
    int blk = blockIdx.x, tid = threadIdx.x;
    if(blk < B_SCAT){
        int b = blk*256 + tid;
        if(b >= NB) return;
        for(int t=0; t<NBOX; t++){
            int c = e_cell[b*NBOX + t];
            if(c >= 0) g_slot[c] = b*NBOX + t;
        }
    } else if(blk < B_SCAT + B_SAME){
        int idx = (blk - B_SCAT)*256 + tid;
        float v = 0.f;
        if(idx < DWROWS*DWCOLS){
            int r = idx >> 10, c = idx & 1023;
            float d = dw[idx] - g_enews[ids[r]*DWCOLS + c];
            v = d*d;
        }
        __shared__ float red[256];
        red[tid] = v; __syncthreads();
        #pragma unroll
        for(int s=128; s>0; s>>=1){ if(tid<s) red[tid]+=red[tid+s]; __syncthreads(); }
        if(tid==0) atomicAdd(&g_acc, (double)red[0]);
    } else {
        int i = blk - (B_SCAT + B_SAME);
        float part[NMETA];
        #pragma unroll
        for(int j=0; j<NMETA; j++) part[j] = 0.f;
        for(int col=tid; col<DWCOLS; col+=256){
            float ei = g_enews[i*DWCOLS + col];
            #pragma unroll
            for(int j=0; j<NMETA; j++){
                float df = ei - g_enews[j*DWCOLS + col];
                part[j] += df*df;
            }
        }
        __shared__ float red[256];
        __shared__ float dmat[NMETA];
        for(int j=0; j<NMETA; j++){
            red[tid] = part[j]; __syncthreads();
            #pragma unroll
            for(int s=128; s>0; s>>=1){ if(tid<s) red[tid]+=red[tid+s]; __syncthreads(); }
            if(tid==0) dmat[j] = red[0];
            __syncthreads();
        }
        if(tid == 0){
            bool pi = g_cnt[i] > 0;
            float dmin = 3.4e38f; bool any = false;
            for(int j=0; j<NMETA; j++){
                bool vp = pi && (g_cnt[j] > 0) && (j != i);
                if(vp){ any = true; dmin = fminf(dmin, dmat[j]); }
            }
            if(any) atomicAdd(&g_acc, -(double)dmin);
        }
    }
}

// ================= Kernel C: main per-cell loss + class loss + finalize =================
__global__ void __launch_bounds__(256) kC(const float* __restrict__ out, float* __restrict__ res){
    int blk = blockIdx.x, tid = threadIdx.x;
    float local = 0.f;
    __shared__ float4 sb[NBOX];
    __shared__ float  sa[NBOX];

    if(blk < C_MAIN){
        int b  = blk / MAIN_BPB;
        int lc = (blk - b*MAIN_BPB)*256 + tid;
        if(tid < NBOX){
            sb[tid] = g_bbox[b*NBOX + tid];
            sa[tid] = g_sarea[b*NBOX + tid];
        }
        __syncthreads();

        if(lc < KPOS){
            int a = lc / AREA; int r = lc - a*AREA;
            const float* p = out + ((b*5+a)*6)*AREA + r;
            float xv = sigmoidf(p[0]);
            float yv = sigmoidf(p[AREA]);
            float wv = p[2*AREA];
            float hv = p[3*AREA];
            float cv = sigmoidf(p[4*AREA]);
            int j = r / NHW, i = r - j*NHW;
            float pw = __expf(wv)*c_aw[a], ph = __expf(hv)*c_ah[a];
            float px = xv + (float)i,  py = yv + (float)j;
            float px1 = px - 0.5f*pw, px2 = px + 0.5f*pw;
            float py1 = py - 0.5f*ph, py2 = py + 0.5f*ph;
            float pa_s = 0.375f*pw*ph;

            // silent  <=>  max_t( inter_t - 0.375*ga_t ) > 0.375*pa
            // clamp only cw: if ch<=0 product<=0 < positive threshold anyway
            float acc = -1e30f;
            #pragma unroll 10
            for(int t=0; t<NBOX; t++){
                float4 bb = sb[t];
                float cw = fminf(px2, bb.z) - fmaxf(px1, bb.x);
                cw = fmaxf(cw, 0.f);
                float ch = fminf(py2, bb.w) - fmaxf(py1, bb.y);
                acc = fmaxf(acc, fmaf(cw, ch, -sa[t]));
            }
            bool silent = acc > pa_s;

            int slot = g_slot[b*KPOS + lc];
            float tx=0.5f, ty=0.5f, tw=0.f, th=0.f, tc=0.f;
            float cm = silent ? 0.f : 1.f;
            if(slot >= 0){
                tx = e_tx[slot]; ty = e_ty[slot]; tw = e_tw[slot];
                th = e_th[slot]; tc = e_tconf[slot]; cm = 5.f;
            }
            float dx = xv - tx, dy = yv - ty, dwv = wv - tw, dh = hv - th, dc = cv - tc;
            local = 0.5f*(dx*dx + dy*dy + dwv*dwv + dh*dh + cm*dc*dc);
        }
    } else {
        int idx = (blk - C_MAIN)*256 + tid;
        if(idx < BS*KPOS){
            int bsi = idx / KPOS; int k = idx - bsi*KPOS;
            int a = k / AREA; int r = k - a*AREA;
            float v[CSZ]; float m = -3.4e38f;
            #pragma unroll
            for(int c=0; c<CSZ; c++){
                int bb = bsi*CSZ + c;
                v[c] = out[(bb*30 + a*6 + 5)*AREA + r];
                m = fmaxf(m, v[c]);
            }
            float s = 0.f;
            #pragma unroll
            for(int c=0; c<CSZ; c++) s += __expf(v[c]-m);
            float lse = m + __logf(s);
            #pragma unroll
            for(int c=0; c<CSZ; c++){
                if(g_slot[(bsi*CSZ + c)*KPOS + k] >= 0) local += lse - v[c];
            }
        }
    }

    // block reduce + global accumulate + last-block finalize
    __shared__ float red[256];
    red[tid] = local; __syncthreads();
    #pragma unroll
    for(int s=128; s>0; s>>=1){ if(tid<s) red[tid]+=red[tid+s]; __syncthreads(); }
    if(tid == 0){
        atomicAdd(&g_acc, (double)red[0]);
        __threadfence();
        int t = atomicAdd(&g_done, 1);
        if(t == C_BLOCKS - 1){
            res[0] = (float)g_acc;   // A,B atomics done (stream order); C's via g_done
        }
    }
}

extern "C" void kernel_launch(void* const* d_in, const int* in_sizes, int n_in,
                              void* d_out, int out_size){
    const float* outp = (const float*)d_in[0];   // (320,30,26,26)
    const float* tgt  = (const float*)d_in[1];   // (16,20,250) == (320,50,5)
    const float* dwp  = (const float*)d_in[2];   // (1,64,1024)
    const int*   ids  = (const int*)d_in[3];     // (64,)
    float* res = (float*)d_out;

    kA<<<A_BLOCKS, 256>>>(outp, tgt, dwp, ids);
    kB<<<B_BLOCKS, 256>>>(dwp, ids);
    kC<<<C_BLOCKS, 256>>>(outp, res);
}

// round 3
// speedup vs baseline: 2.0222x; 1.2409x over previous
#include <cuda_runtime.h>

#define NB     320
#define NHW    26
#define AREA   676          // 26*26
#define KPOS   3380         // 5*676
#define NBOX   50
#define NENT   (NB*NBOX)    // 16000
#define BS     16
#define CSZ    20
#define NMETA  20
#define DWROWS 64
#define DWCOLS 1024

// kernel A block layout
#define A_ENT   63                  // ceil(16000/256)
#define A_ENEW  20
#define A_BLOCKS (A_ENT + A_ENEW)
// kernel C block layout
#define MAIN_BPB 4                  // 1024 cells per block (256 thr * 4)
#define C_MAIN  (NB*MAIN_BPB)       // 1280
#define C_CORR  63                  // ceil(16000/256)
#define C_SAME  64                  // 65536 elems / (256*4)
#define C_DIFF  20
#define C_BLOCKS (C_MAIN + C_CORR + C_SAME + C_DIFF)

__constant__ float c_aw[5] = {1.3221f, 3.19275f, 5.05587f, 9.47112f, 11.2364f};
__constant__ float c_ah[5] = {1.73145f, 4.00944f, 8.09892f, 4.84053f, 10.0071f};

__device__ double g_acc;
__device__ int    g_done;
__device__ float  e_tx[NENT], e_ty[NENT], e_tw[NENT], e_th[NENT], e_tconf[NENT];
__device__ int    e_cell[NENT];     // global cell id (b*KPOS + ...) or -1
__device__ float4 g_bbox[NENT];
__device__ float  g_sarea[NENT];    // 0.375 * gw*gh
__device__ float  g_enews[NMETA*DWCOLS];
__device__ int    g_cnt[NMETA];

__device__ __forceinline__ float sigmoidf(float v){ return 1.f/(1.f+__expf(-v)); }

// ================= Kernel A: entries + class means + init =================
__global__ void __launch_bounds__(256) kA(const float* __restrict__ out,
                                          const float* __restrict__ tgt,
                                          const float* __restrict__ dw,
                                          const int*   __restrict__ ids){
    int blk = blockIdx.x, tid = threadIdx.x;
    if(blk < A_ENT){
        if(blk == 0 && tid == 0){ g_acc = 0.0; g_done = 0; }
        int e = blk*256 + tid;
        if(e >= NENT) return;
        int b = e / NBOX;
        const float* g = tgt + e*5;
        float g1 = g[1];
        if(g1 == 0.0f){
            e_cell[e]  = -1;
            g_bbox[e]  = make_float4(3e9f, 3e9f, 3e9f, 3e9f);  // degenerate: never silences
            g_sarea[e] = 1.0f;
            return;
        }
        float gx = g1*26.f, gy = g[2]*26.f, gw = g[3]*26.f, gh = g[4]*26.f;
        g_bbox[e]  = make_float4(gx-0.5f*gw, gy-0.5f*gh, gx+0.5f*gw, gy+0.5f*gh);
        g_sarea[e] = 0.375f*gw*gh;

        int bn = 0; float best = -1.f;
        #pragma unroll
        for(int a=0; a<5; a++){
            float inter = fminf(gw, c_aw[a]) * fminf(gh, c_ah[a]);
            float iou = inter / (gw*gh + c_aw[a]*c_ah[a] - inter);
            if(iou > best){ best = iou; bn = a; }
        }
        int gi = (int)gx; gi = min(max(gi,0), NHW-1);
        int gj = (int)gy; gj = min(max(gj,0), NHW-1);

        int base = ((b*5+bn)*6)*AREA + gj*NHW + gi;
        float px = sigmoidf(out[base])          + (float)gi;
        float py = sigmoidf(out[base+AREA])     + (float)gj;
        float pw = __expf(out[base+2*AREA]) * c_aw[bn];
        float ph = __expf(out[base+3*AREA]) * c_ah[bn];

        float cw  = fminf(gx+0.5f*gw, px+0.5f*pw) - fmaxf(gx-0.5f*gw, px-0.5f*pw);
        float chh = fminf(gy+0.5f*gh, py+0.5f*ph) - fmaxf(gy-0.5f*gh, py-0.5f*ph);
        float inter = (cw>0.f && chh>0.f) ? cw*chh : 0.f;
        float iou = inter / (gw*gh + pw*ph - inter);

        e_tx[e] = gx - (float)gi;
        e_ty[e] = gy - (float)gj;
        e_tw[e] = logf(gw / c_aw[bn]);
        e_th[e] = logf(gh / c_ah[bn]);
        e_tconf[e] = iou;
        e_cell[e] = b*KPOS + bn*AREA + gj*NHW + gi;
    } else {
        // per-class mean embeddings: one block per class
        int c = blk - A_ENT;
        __shared__ int sids[DWROWS];
        if(tid < DWROWS) sids[tid] = ids[tid];
        __syncthreads();
        int n = 0;
        #pragma unroll
        for(int r=0; r<DWROWS; r++) n += (sids[r] == c);
        if(tid == 0) g_cnt[c] = n;
        float inv = 1.f / (float)max(n, 1);
        for(int col = tid; col < DWCOLS; col += 256){
            float s = 0.f;
            #pragma unroll
            for(int r=0; r<DWROWS; r++){
                if(sids[r] == c) s += dw[r*DWCOLS + col];
            }
            g_enews[c*DWCOLS + col] = s * inv;
        }
    }
}

// ================= Kernel C: everything else, fused =================
__global__ void __launch_bounds__(256) kC(const float* __restrict__ out,
                                          const float* __restrict__ dw,
                                          const int*   __restrict__ ids,
                                          float* __restrict__ res){
    int blk = blockIdx.x, tid = threadIdx.x;
    float local = 0.f;

    if(blk < C_MAIN){
        // ---- default per-cell loss, 4 cells/thread ----
        int b     = blk >> 2;
        int chunk = blk & 3;
        int lc0   = chunk*1024 + tid*4;

        __shared__ float4 sb[NBOX];
        __shared__ float  sa[NBOX];
        if(tid < NBOX){
            sb[tid] = g_bbox[b*NBOX + tid];
            sa[tid] = g_sarea[b*NBOX + tid];
        }
        __syncthreads();

        if(lc0 < KPOS){
            int a  = lc0 / AREA;
            int r0 = lc0 - a*AREA;
            const float* p = out + ((b*5+a)*6)*AREA + r0;
            float4 xr = *(const float4*)(p);
            float4 yr = *(const float4*)(p +   AREA);
            float4 wr = *(const float4*)(p + 2*AREA);
            float4 hr = *(const float4*)(p + 3*AREA);
            float4 cr = *(const float4*)(p + 4*AREA);
            float xv[4] = {sigmoidf(xr.x), sigmoidf(xr.y), sigmoidf(xr.z), sigmoidf(xr.w)};
            float yv[4] = {sigmoidf(yr.x), sigmoidf(yr.y), sigmoidf(yr.z), sigmoidf(yr.w)};
            float wv[4] = {wr.x, wr.y, wr.z, wr.w};
            float hv[4] = {hr.x, hr.y, hr.z, hr.w};
            float cv[4] = {sigmoidf(cr.x), sigmoidf(cr.y), sigmoidf(cr.z), sigmoidf(cr.w)};

            float px1[4], px2[4], py1[4], py2[4], pas[4], acc[4];
            #pragma unroll
            for(int u=0; u<4; u++){
                int r = r0 + u;
                int j = r / NHW, i = r - j*NHW;
                float pw = __expf(wv[u])*c_aw[a], ph = __expf(hv[u])*c_ah[a];
                float px = xv[u] + (float)i, py = yv[u] + (float)j;
                px1[u] = px - 0.5f*pw; px2[u] = px + 0.5f*pw;
                py1[u] = py - 0.5f*ph; py2[u] = py + 0.5f*ph;
                pas[u] = 0.375f*pw*ph;
                acc[u] = -1e30f;
            }
            #pragma unroll 10
            for(int t=0; t<NBOX; t++){
                float4 bb = sb[t];
                float s  = sa[t];
                #pragma unroll
                for(int u=0; u<4; u++){
                    float cw = fminf(px2[u], bb.z) - fmaxf(px1[u], bb.x);
                    cw = fmaxf(cw, 0.f);
                    float ch = fminf(py2[u], bb.w) - fmaxf(py1[u], bb.y);
                    acc[u] = fmaxf(acc[u], fmaf(cw, ch, -s));
                }
            }
            #pragma unroll
            for(int u=0; u<4; u++){
                float cm = (acc[u] > pas[u]) ? 0.f : 1.f;
                float dx = xv[u]-0.5f, dy = yv[u]-0.5f;
                local += 0.5f*(dx*dx + dy*dy + wv[u]*wv[u] + hv[u]*hv[u] + cm*cv[u]*cv[u]);
            }
        }
    } else if(blk < C_MAIN + C_CORR){
        // ---- correction for matched (winner) entries ----
        int e = (blk - C_MAIN)*256 + tid;
        if(e < NENT){
            int cell = e_cell[e];
            if(cell >= 0){
                int b = e / NBOX, t0 = e - b*NBOX;
                bool winner = true;
                for(int t2 = t0+1; t2 < NBOX; t2++)
                    winner &= (e_cell[b*NBOX + t2] != cell);
                if(winner){
                    int k = cell - b*KPOS;
                    int a = k / AREA, r = k - a*AREA;
                    const float* p = out + ((b*5+a)*6)*AREA + r;
                    float xv = sigmoidf(p[0]);
                    float yv = sigmoidf(p[AREA]);
                    float wv = p[2*AREA];
                    float hv = p[3*AREA];
                    float cvv = sigmoidf(p[4*AREA]);
                    // recompute silent (same math as main)
                    int j = r / NHW, i = r - j*NHW;
                    float pw = __expf(wv)*c_aw[a], ph = __expf(hv)*c_ah[a];
                    float px = xv + (float)i, py = yv + (float)j;
                    float px1 = px-0.5f*pw, px2 = px+0.5f*pw;
                    float py1 = py-0.5f*ph, py2 = py+0.5f*ph;
                    float pas = 0.375f*pw*ph;
                    float acc = -1e30f;
                    for(int t=0; t<NBOX; t++){
                        float4 bb = g_bbox[b*NBOX + t];
                        float cw = fminf(px2, bb.z) - fmaxf(px1, bb.x);
                        cw = fmaxf(cw, 0.f);
                        float ch = fminf(py2, bb.w) - fmaxf(py1, bb.y);
                        acc = fmaxf(acc, fmaf(cw, ch, -g_sarea[b*NBOX + t]));
                    }
                    float cmd = (acc > pas) ? 0.f : 1.f;
                    float dx0 = xv-0.5f, dy0 = yv-0.5f;
                    float ldft = 0.5f*(dx0*dx0 + dy0*dy0 + wv*wv + hv*hv + cmd*cvv*cvv);
                    float dx = xv-e_tx[e], dy = yv-e_ty[e], dwv = wv-e_tw[e],
                          dh = hv-e_th[e], dc = cvv-e_tconf[e];
                    float lmat = 0.5f*(dx*dx + dy*dy + dwv*dwv + dh*dh + 5.f*dc*dc);
                    // class loss for this cell: log-softmax over the 20-image group
                    int bsi = b / CSZ, cc = b - bsi*CSZ;
                    float v[CSZ]; float m = -3.4e38f;
                    #pragma unroll
                    for(int c2=0; c2<CSZ; c2++){
                        v[c2] = out[((bsi*CSZ+c2)*30 + a*6 + 5)*AREA + r];
                        m = fmaxf(m, v[c2]);
                    }
                    float s = 0.f;
                    #pragma unroll
                    for(int c2=0; c2<CSZ; c2++) s += __expf(v[c2]-m);
                    float lse = m + __logf(s);
                    local = lmat - ldft + (lse - v[cc]);
                }
            }
        }
    } else if(blk < C_MAIN + C_CORR + C_SAME){
        // ---- "same" loss, float4 per thread ----
        int idx4 = (blk - (C_MAIN + C_CORR))*256 + tid;
        int base = idx4*4;
        int r = base >> 10, c = base & 1023;
        float4 d  = *(const float4*)(dw + base);
        const float* en = g_enews + ids[r]*DWCOLS + c;
        float4 ev = *(const float4*)en;
        float a0 = d.x-ev.x, a1 = d.y-ev.y, a2 = d.z-ev.z, a3 = d.w-ev.w;
        local = a0*a0 + a1*a1 + a2*a2 + a3*a3;
    } else {
        // ---- pairwise distances + "different" loss ----
        int i = blk - (C_MAIN + C_CORR + C_SAME);
        float part[NMETA];
        #pragma unroll
        for(int j=0; j<NMETA; j++) part[j] = 0.f;
        for(int col=tid; col<DWCOLS; col+=256){
            float ei = g_enews[i*DWCOLS + col];
            #pragma unroll
            for(int j=0; j<NMETA; j++){
                float df = ei - g_enews[j*DWCOLS + col];
                part[j] += df*df;
            }
        }
        __shared__ float red2[256];
        __shared__ float dmat[NMETA];
        for(int j=0; j<NMETA; j++){
            red2[tid] = part[j]; __syncthreads();
            #pragma unroll
            for(int s=128; s>0; s>>=1){ if(tid<s) red2[tid]+=red2[tid+s]; __syncthreads(); }
            if(tid==0) dmat[j] = red2[0];
            __syncthreads();
        }
        if(tid == 0){
            bool pi = g_cnt[i] > 0;
            float dmin = 3.4e38f; bool any = false;
            for(int j=0; j<NMETA; j++){
                bool vp = pi && (g_cnt[j] > 0) && (j != i);
                if(vp){ any = true; dmin = fminf(dmin, dmat[j]); }
            }
            if(any) local = -dmin;
        }
    }

    // block reduce + global accumulate + last-block finalize
    __shared__ float red[256];
    red[tid] = local; __syncthreads();
    #pragma unroll
    for(int s=128; s>0; s>>=1){ if(tid<s) red[tid]+=red[tid+s]; __syncthreads(); }
    if(tid == 0){
        atomicAdd(&g_acc, (double)red[0]);
        __threadfence();
        int t = atomicAdd(&g_done, 1);
        if(t == C_BLOCKS - 1){
            res[0] = (float)g_acc;
        }
    }
}

extern "C" void kernel_launch(void* const* d_in, const int* in_sizes, int n_in,
                              void* d_out, int out_size){
    const float* outp = (const float*)d_in[0];   // (320,30,26,26)
    const float* tgt  = (const float*)d_in[1];   // (16,20,250) == (320,50,5)
    const float* dwp  = (const float*)d_in[2];   // (1,64,1024)
    const int*   ids  = (const int*)d_in[3];     // (64,)
    float* res = (float*)d_out;

    kA<<<A_BLOCKS, 256>>>(outp, tgt, dwp, ids);
    kC<<<C_BLOCKS, 256>>>(outp, dwp, ids, res);
}